// round 17
// baseline (speedup 1.0000x reference)
#include <cuda_runtime.h>
#include <cstdint>

#define BN 32
#define AN 8400
#define CN 80
#define MN 64
#define TK 13
#define EPSF 1e-9f
#define NB 32                 // bins per dim
#define BINV 0.05f            // 1 / 20px
#define NBINS (NB*NB)
#define NF4   (BN*AN*CN/4)    // 5,376,000 float4s in score tensor
#define NBLK  592             // 148 SMs x 4 blocks -- all resident (GB300 has 152)
#define NTHR  256
#define NCHUNK (33*BN)        // 256-anchor chunks: ceil(8400/256)=33 per batch

// ---------------- scratch (device globals; no allocation) ----------------
__device__ int    d_claim[BN*AN];     // (cnt<<16) | sum_of_m
__device__ float  d_maxmet[BN*MN];
__device__ float  d_maxiou[BN*MN];
__device__ int    d_ma[BN*AN];
__device__ float  d_alignv[BN*AN];
__device__ int    d_binstart[NBINS+1];
__device__ float2 d_bin_pt[AN];
__device__ int    d_bin_aid[AN];

// grid barrier state (phase keeps incrementing across graph replays; count
// returns to 0 at every release -> deterministic behavior every call)
__device__ unsigned g_count = 0u;
__device__ volatile unsigned g_phase = 0u;

__device__ __forceinline__ void gsync() {
    __syncthreads();
    if (threadIdx.x == 0) {
        __threadfence();
        unsigned ph = g_phase;
        if (atomicAdd(&g_count, 1u) == NBLK - 1u) {
            atomicExch(&g_count, 0u);
            __threadfence();
            g_phase = ph + 1u;
        } else {
            while (g_phase == ph) __nanosleep(64);
        }
        __threadfence();
    }
    __syncthreads();
}

__global__ void __launch_bounds__(NTHR, 4)
k_all(const float* __restrict__ ps, const float* __restrict__ pb,
      const float* __restrict__ ap, const int* __restrict__ gl,
      const float* __restrict__ gb, const float* __restrict__ pad,
      const int* __restrict__ bgp,
      float* __restrict__ outL, float* __restrict__ outB,
      float* __restrict__ outS, float4* __restrict__ outS4)
{
    __shared__ int   s_cnt[NBINS];
    __shared__ int   s_cur[NBINS];
    __shared__ int   s_wsc[8];
    __shared__ float s_v[4][2][TK];
    __shared__ int   s_i[4][2][TK];
    __shared__ float4 s_gbox[MN];
    __shared__ float  s_gar[MN];
    __shared__ int    s_lab[MN];

    const int tid  = threadIdx.x;
    const int blk  = blockIdx.x;
    const int lane = tid & 31;
    const int wid  = tid >> 5;

    // ================= stage 0: binning (block 0) | zero+fill (others) =====
    if (blk == 0) {
        const float2* ap2 = reinterpret_cast<const float2*>(ap);
        for (int i = tid; i < NBINS; i += NTHR) s_cnt[i] = 0;
        __syncthreads();
        for (int i = tid; i < AN; i += NTHR) {
            float2 pt = ap2[i];
            int bx = min(NB-1, max(0, (int)(pt.x * BINV)));
            int by = min(NB-1, max(0, (int)(pt.y * BINV)));
            atomicAdd(&s_cnt[by*NB + bx], 1);
        }
        __syncthreads();
        // exclusive scan of 1024 counts with 256 threads (4 bins/thread)
        int c0 = s_cnt[4*tid], c1 = s_cnt[4*tid+1], c2 = s_cnt[4*tid+2], c3 = s_cnt[4*tid+3];
        int tsum = c0 + c1 + c2 + c3;
        int x = tsum;
        #pragma unroll
        for (int o = 1; o < 32; o <<= 1) {
            int y = __shfl_up_sync(0xffffffffu, x, o);
            if (lane >= o) x += y;
        }
        if (lane == 31) s_wsc[wid] = x;
        __syncthreads();
        if (tid == 0) {
            int acc = 0;
            #pragma unroll
            for (int j = 0; j < 8; j++) { int t = s_wsc[j]; s_wsc[j] = acc; acc += t; }
        }
        __syncthreads();
        int e0 = x - tsum + s_wsc[wid];
        int e1 = e0 + c0, e2 = e1 + c1, e3 = e2 + c2;
        d_binstart[4*tid]   = e0; d_binstart[4*tid+1] = e1;
        d_binstart[4*tid+2] = e2; d_binstart[4*tid+3] = e3;
        s_cur[4*tid] = e0; s_cur[4*tid+1] = e1; s_cur[4*tid+2] = e2; s_cur[4*tid+3] = e3;
        if (tid == NTHR-1) d_binstart[NBINS] = e3 + c3;   // == AN
        __syncthreads();
        for (int i = tid; i < AN; i += NTHR) {
            float2 pt = ap2[i];
            int bx = min(NB-1, max(0, (int)(pt.x * BINV)));
            int by = min(NB-1, max(0, (int)(pt.y * BINV)));
            int pos = atomicAdd(&s_cur[by*NB + bx], 1);
            d_bin_pt[pos]  = pt;
            d_bin_aid[pos] = i;
        }
    } else {
        int t = (blk - 1)*NTHR + tid;
        int step = (NBLK - 1)*NTHR;
        for (int i = t; i < BN*AN; i += step) d_claim[i] = 0;
        if (blk == 1)
            for (int i = tid; i < BN*MN; i += NTHR) { d_maxmet[i] = 0.f; d_maxiou[i] = 0.f; }
        const float4 z = make_float4(0.f,0.f,0.f,0.f);
        for (int i = t; i < NF4; i += step) outS4[i] = z;   // drains during stages 1-2
    }
    gsync();

    // ================= stage 1: top-13, blocks 0..511, 4 gts x 2 warps =====
    if (blk < 512) {
        const int gslot = wid >> 1;
        const int half  = wid & 1;
        const int W = blk*4 + gslot;          // gt id < 2048
        const int b = W >> 6;
        const int m = W & 63;
        const bool active = pad[b*MN + m] >= 0.5f;

        if (active) {
            const float4 g = reinterpret_cast<const float4*>(gb)[b*MN + m];
            const float gar = fmaxf(g.z - g.x, 0.f) * fmaxf(g.w - g.y, 0.f);
            const int lab = gl[b*MN + m];
            const float4* pb4 = reinterpret_cast<const float4*>(pb) + (size_t)b*AN;
            const float*  psb = ps + (size_t)b*AN*CN + lab;

            const int c0 = min(NB-1, max(0, (int)(g.x * BINV)));
            const int c1 = min(NB-1, max(0, (int)(g.z * BINV)));
            const int r0 = min(NB-1, max(0, (int)(g.y * BINV)));
            const int r1 = min(NB-1, max(0, (int)(g.w * BINV)));

            float tv[TK]; int ti[TK];
            #pragma unroll
            for (int k = 0; k < TK; k++) { tv[k] = 0.f; ti[k] = -1; }

            for (int r = r0 + half; r <= r1; r += 2) {
                const int s = d_binstart[r*NB + c0];
                const int e = d_binstart[r*NB + c1 + 1];   // contiguous span
                for (int i0 = s; i0 < e; i0 += 32) {
                    const int i = i0 + lane;
                    bool inside = false;
                    if (i < e) {
                        float2 pt = d_bin_pt[i];
                        float dmin = fminf(fminf(pt.x - g.x, pt.y - g.y),
                                           fminf(g.z - pt.x, g.w - pt.y));
                        inside = dmin > EPSF;
                    }
                    if (__ballot_sync(0xffffffffu, inside)) {
                        float metr = 0.f; int aid = -1;
                        if (inside) {
                            aid = d_bin_aid[i];
                            float4 p = pb4[aid];
                            float parea = fmaxf(p.z - p.x, 0.f) * fmaxf(p.w - p.y, 0.f);
                            float ox = fminf(g.z, p.z) - fmaxf(g.x, p.x);
                            float oy = fminf(g.w, p.w) - fmaxf(g.y, p.y);
                            float ov = fmaxf(ox, 0.f) * fmaxf(oy, 0.f);
                            float iou = __fdividef(ov, gar + parea - ov + EPSF);
                            float sc = __ldg(psb + (size_t)aid*CN);
                            float i2 = iou * iou;
                            metr = sc * (i2 * i2 * i2);      // score^1 * iou^6
                        }
                        if (metr > tv[TK-1]) {
                            tv[TK-1] = metr; ti[TK-1] = aid;
                            #pragma unroll
                            for (int k = TK-1; k > 0; --k) {
                                if (tv[k] > tv[k-1]) {
                                    float xx = tv[k]; tv[k] = tv[k-1]; tv[k-1] = xx;
                                    int   yy = ti[k]; ti[k] = ti[k-1]; ti[k-1] = yy;
                                }
                            }
                        }
                    }
                }
            }

            // this warp's sorted top-13 -> smem (desc, tie -> lower index)
            #pragma unroll
            for (int r = 0; r < TK; r++) {
                float v = tv[0]; int idx = ti[0];
                #pragma unroll
                for (int o = 16; o; o >>= 1) {
                    float ov = __shfl_xor_sync(0xffffffffu, v, o);
                    int   oi = __shfl_xor_sync(0xffffffffu, idx, o);
                    if (ov > v || (ov == v && (unsigned)oi < (unsigned)idx)) { v = ov; idx = oi; }
                }
                if (lane == r) { s_v[gslot][half][r] = v; s_i[gslot][half][r] = idx; }
                if (v > 0.f && idx == ti[0]) {            // unique winner lane pops
                    #pragma unroll
                    for (int j = 0; j < TK-1; j++) { tv[j] = tv[j+1]; ti[j] = ti[j+1]; }
                    tv[TK-1] = 0.f; ti[TK-1] = -1;
                }
            }
        } else {
            if (lane < TK) { s_v[gslot][half][lane] = 0.f; s_i[gslot][half][lane] = -1; }
        }
        __syncthreads();

        // warp half==0 merges the two sorted 13-lists (guarded; 26 entries)
        if (half == 0 && active) {
            float v = 0.f; int idx = -1;
            if (lane < 2*TK) {
                int h = lane >= TK;
                int k = lane - h*TK;
                v   = s_v[gslot][h][k];
                idx = s_i[gslot][h][k];
            }
            #pragma unroll
            for (int r = 0; r < TK; r++) {
                float rv = v; int ridx = idx;
                #pragma unroll
                for (int o = 16; o; o >>= 1) {
                    float ov = __shfl_xor_sync(0xffffffffu, rv, o);
                    int   oi = __shfl_xor_sync(0xffffffffu, ridx, o);
                    if (ov > rv || (ov == rv && (unsigned)oi < (unsigned)ridx)) { rv = ov; ridx = oi; }
                }
                if (rv <= 0.f) break;                     // uniform
                if (v == rv && idx == ridx) {             // unique owner
                    atomicAdd(&d_claim[b*AN + idx], (1 << 16) + m);
                    v = 0.f; idx = -1;
                }
            }
        }
    }
    gsync();

    // ================= stage 2: per-anchor assignment ======================
    {
        const int bgv = bgp ? *bgp : 80;
        for (int ch = blk; ch < NCHUNK; ch += NBLK) {
            int b  = ch / 33;
            int a0 = (ch - b*33) * 256;
            __syncthreads();                 // protect smem tables across iters
            if (tid < MN) {
                float4 g = reinterpret_cast<const float4*>(gb)[b*MN + tid];
                s_gbox[tid] = g;
                s_gar[tid]  = fmaxf(g.z - g.x, 0.f) * fmaxf(g.w - g.y, 0.f);
                s_lab[tid]  = gl[b*MN + tid];
            }
            __syncthreads();
            int a = a0 + tid;
            if (a < AN) {
                int idx = b*AN + a;
                int claim = d_claim[idx];
                int c = claim >> 16;
                if (c == 0) {                       // ~92%: background
                    d_ma[idx] = -1;
                    outL[idx] = (float)bgv;
                    reinterpret_cast<float4*>(outB)[idx] = s_gbox[0];
                } else {
                    float4 p = reinterpret_cast<const float4*>(pb)[idx];
                    float parea = fmaxf(p.z - p.x, 0.f) * fmaxf(p.w - p.y, 0.f);
                    int m_a;
                    if (c == 1) m_a = claim & 0xffff;
                    else {                          // multi: argmax IoU over ALL gts
                        float best = -1.f; int bi2 = 0;
                        for (int m = 0; m < MN; m++) {
                            float4 g = s_gbox[m];
                            float ox = fminf(g.z, p.z) - fmaxf(g.x, p.x);
                            float oy = fminf(g.w, p.w) - fmaxf(g.y, p.y);
                            float ov = fmaxf(ox, 0.f) * fmaxf(oy, 0.f);
                            float iou = __fdividef(ov, s_gar[m] + parea - ov + EPSF);
                            if (iou > best) { best = iou; bi2 = m; }
                        }
                        m_a = bi2;
                    }
                    float4 g = s_gbox[m_a];
                    float ox = fminf(g.z, p.z) - fmaxf(g.x, p.x);
                    float oy = fminf(g.w, p.w) - fmaxf(g.y, p.y);
                    float ov = fmaxf(ox, 0.f) * fmaxf(oy, 0.f);
                    float iou = __fdividef(ov, s_gar[m_a] + parea - ov + EPSF);
                    float s = __ldg(ps + (size_t)idx*CN + s_lab[m_a]);
                    float i2 = iou * iou;
                    float alignv = s * (i2 * i2 * i2);
                    atomicMax((int*)&d_maxmet[b*MN + m_a], __float_as_int(alignv));
                    atomicMax((int*)&d_maxiou[b*MN + m_a], __float_as_int(iou));
                    d_ma[idx] = m_a;
                    d_alignv[idx] = alignv;
                    outL[idx] = (float)s_lab[m_a];
                    reinterpret_cast<float4*>(outB)[idx] = g;
                }
            }
        }
    }
    gsync();

    // ================= stage 3: sparse score scatter =======================
    for (int i = blk*NTHR + tid; i < BN*AN; i += NBLK*NTHR) {
        int m_a = d_ma[i];
        if (m_a >= 0) {
            int b = i / AN;
            int bm = b*MN + m_a;
            float s = __fdividef(d_alignv[i], d_maxmet[bm] + EPSF) * d_maxiou[bm];
            outS[(size_t)i*CN + gl[bm]] = s;
        }
    }
}

// ---------------- launch ----------------
extern "C" void kernel_launch(void* const* d_in, const int* in_sizes, int n_in,
                              void* d_out, int out_size)
{
    const float* ps  = (const float*)d_in[0];   // pred_scores  (B,A,C)
    const float* pb  = (const float*)d_in[1];   // pred_bboxes  (B,A,4)
    const float* ap  = (const float*)d_in[2];   // anchor_points(A,2)
    const int*   gl  = (const int*)d_in[3];     // gt_labels    (B,M,1)
    const float* gb  = (const float*)d_in[4];   // gt_bboxes    (B,M,4)
    const float* pad = (const float*)d_in[5];   // pad_gt_mask  (B,M,1)
    const int*   bg  = (n_in >= 7) ? (const int*)d_in[6] : nullptr;

    float* outL = (float*)d_out;                       // labels  (B*A)
    float* outB = outL + (size_t)BN*AN;                // bboxes  (B*A*4)
    float* outS = outL + (size_t)BN*AN*5;              // scores  (B*A*C)

    k_all<<<NBLK, NTHR>>>(ps, pb, ap, gl, gb, pad, bg, outL, outB,
                          outS, reinterpret_cast<float4*>(outS));
}